// round 4
// baseline (speedup 1.0000x reference)
#include <cuda_runtime.h>
#include <cuda_bf16.h>
#include <cstdint>

// Problem constants
#define N_ROWS 16384
#define M_ROWS 1024
#define D_DIM  256
#define OUT_EPS 1e-6f

// GEMM tiling (tf32: BK=16 keeps double-buffered fp32 smem under 48KB)
#define BM 128
#define BN 128
#define BK 16
#define KPAD 4
#define KSTRIDE (BK + KPAD)   // 20 floats = 80 bytes row stride (16B aligned)

// Scratch (allocation-free rule: __device__ globals). tf32-rounded fp32.
__device__ float g_xb[N_ROWS * D_DIM];
__device__ float g_pb[M_ROWS * D_DIM];
__device__ float g_xn[N_ROWS];
__device__ float g_pn[M_ROWS];

__device__ __forceinline__ float to_tf32(float v)
{
    float r;
    asm("cvt.rna.tf32.f32 %0, %1;" : "=f"(r) : "f"(v));
    return r;
}

// ---------------------------------------------------------------------------
// Prep: wv = v * fw ; store tf32-rounded fp32 ; norm = sum(wv^2) exact fp32.
// One warp per row.
// ---------------------------------------------------------------------------
__global__ void prep_kernel(const float* __restrict__ src,
                            const float* __restrict__ fw,
                            int rows, int which)
{
    int gw   = (blockIdx.x * blockDim.x + threadIdx.x) >> 5;
    int lane = threadIdx.x & 31;
    if (gw >= rows) return;

    float* dst   = which ? g_pb : g_xb;
    float* norms = which ? g_pn : g_xn;

    const float* r = src + (size_t)gw * D_DIM;
    float* o = dst + (size_t)gw * D_DIM;

    float s = 0.f;
#pragma unroll
    for (int i = 0; i < D_DIM / 32; ++i) {
        int c = lane + 32 * i;
        float v = r[c] * fw[c];
        s = fmaf(v, v, s);
        o[c] = to_tf32(v);
    }
#pragma unroll
    for (int off = 16; off; off >>= 1)
        s += __shfl_xor_sync(0xffffffffu, s, off);
    if (lane == 0) norms[gw] = s;
}

// ---------------------------------------------------------------------------
// asm helpers
// ---------------------------------------------------------------------------
__device__ __forceinline__ void cp_async_16(void* smem_dst, const void* gmem_src)
{
    uint32_t daddr = (uint32_t)__cvta_generic_to_shared(smem_dst);
    asm volatile("cp.async.cg.shared.global [%0], [%1], 16;"
                 :: "r"(daddr), "l"(gmem_src) : "memory");
}

__device__ __forceinline__ void cp_async_commit()
{
    asm volatile("cp.async.commit_group;" ::: "memory");
}

template <int NWait>
__device__ __forceinline__ void cp_async_wait()
{
    asm volatile("cp.async.wait_group %0;" :: "n"(NWait) : "memory");
}

__device__ __forceinline__ void mma_tf32(float* c, const uint32_t* a, const uint32_t* b)
{
    asm volatile(
        "mma.sync.aligned.m16n8k8.row.col.f32.tf32.tf32.f32 "
        "{%0,%1,%2,%3}, {%4,%5,%6,%7}, {%8,%9}, {%0,%1,%2,%3};"
        : "+f"(c[0]), "+f"(c[1]), "+f"(c[2]), "+f"(c[3])
        : "r"(a[0]), "r"(a[1]), "r"(a[2]), "r"(a[3]),
          "r"(b[0]), "r"(b[1]));
}

// ---------------------------------------------------------------------------
// Fused GEMM + epilogue.
// dot[i,j] = wx[i,:] . wp[j,:]   (tf32 mma.sync m16n8k8, fp32 accum)
// sq = xn[i] + pn[j] - 2*dot ; d = sqrt(max(sq,0)+eps) ; s = exp(-T*d)
// out[0 .. N*M) = similarities ; out[N*M .. 2*N*M) = distances
// ---------------------------------------------------------------------------
__global__ __launch_bounds__(256, 2)
void gemm_kernel(const float* __restrict__ tptr, float* __restrict__ out)
{
    __shared__ float sA[2][BM][KSTRIDE];
    __shared__ float sB[2][BN][KSTRIDE];

    const int tid  = threadIdx.x;
    const int warp = tid >> 5;
    const int lane = tid & 31;
    const int bm   = blockIdx.y;   // N tile
    const int bn   = blockIdx.x;   // M tile

    const int wm = (warp >> 2) * 64;  // warp row offset within 128 (2 warps)
    const int wn = (warp & 3) * 32;   // warp col offset within 128 (4 warps)

    const int g = lane >> 2;          // groupID   (0..7)
    const int t = lane & 3;           // tid-in-group (0..3)

    float acc[4][4][4];
#pragma unroll
    for (int i = 0; i < 4; ++i)
#pragma unroll
        for (int j = 0; j < 4; ++j)
#pragma unroll
            for (int k = 0; k < 4; ++k) acc[i][j][k] = 0.f;

    const float* gA = g_xb + (size_t)bm * BM * D_DIM;
    const float* gB = g_pb + (size_t)bn * BN * D_DIM;

    // Stage loader: per tile 128 rows x 16 floats = 512 x 16B chunks;
    // 256 threads -> 2 chunks each per tile (A and B).
    const int row0 = tid >> 2;           // 0..63
    const int c0   = (tid & 3) * 4;      // float index 0,4,8,12
    const int row1 = row0 + 64;          // 64..127

    const int NK = D_DIM / BK;  // 16

#pragma unroll 1
    for (int kt = -1; kt < NK; ++kt) {
        int ktn = kt + 1;
        if (ktn < NK) {
            int buf = ktn & 1;
            int k0  = ktn * BK;
            cp_async_16(&sA[buf][row0][c0], gA + (size_t)row0 * D_DIM + k0 + c0);
            cp_async_16(&sB[buf][row0][c0], gB + (size_t)row0 * D_DIM + k0 + c0);
            cp_async_16(&sA[buf][row1][c0], gA + (size_t)row1 * D_DIM + k0 + c0);
            cp_async_16(&sB[buf][row1][c0], gB + (size_t)row1 * D_DIM + k0 + c0);
            cp_async_commit();
        }
        if (kt < 0) { cp_async_wait<0>(); __syncthreads(); continue; }
        if (ktn < NK) cp_async_wait<1>(); else cp_async_wait<0>();

        const int buf = kt & 1;
#pragma unroll
        for (int ks = 0; ks < BK / 8; ++ks) {
            const int k0 = ks * 8;
            uint32_t af[4][4];
            uint32_t bf[4][2];
#pragma unroll
            for (int mt = 0; mt < 4; ++mt) {
                const int r = wm + mt * 16;
                af[mt][0] = __float_as_uint(sA[buf][r + g    ][k0 + t    ]);
                af[mt][1] = __float_as_uint(sA[buf][r + g + 8][k0 + t    ]);
                af[mt][2] = __float_as_uint(sA[buf][r + g    ][k0 + t + 4]);
                af[mt][3] = __float_as_uint(sA[buf][r + g + 8][k0 + t + 4]);
            }
#pragma unroll
            for (int nt = 0; nt < 4; ++nt) {
                const int c = wn + nt * 8;
                bf[nt][0] = __float_as_uint(sB[buf][c + g][k0 + t    ]);
                bf[nt][1] = __float_as_uint(sB[buf][c + g][k0 + t + 4]);
            }
#pragma unroll
            for (int mt = 0; mt < 4; ++mt)
#pragma unroll
                for (int nt = 0; nt < 4; ++nt)
                    mma_tf32(acc[mt][nt], af[mt], bf[nt]);
        }
        __syncthreads();
    }

    // ----- fused epilogue -----
    const float temp = *tptr;
    const int grow0 = bm * BM + wm + g;
    const int gcol0 = bn * BN + wn + 2 * t;

    float* simo  = out;
    float* disto = out + (size_t)N_ROWS * M_ROWS;

#pragma unroll
    for (int mt = 0; mt < 4; ++mt) {
        const int r0 = grow0 + mt * 16;
        const float xn0 = g_xn[r0];
        const float xn1 = g_xn[r0 + 8];
#pragma unroll
        for (int nt = 0; nt < 4; ++nt) {
            const int c = gcol0 + nt * 8;
            const float pn0 = g_pn[c];
            const float pn1 = g_pn[c + 1];

            // acc layout: [0]:(r0,c) [1]:(r0,c+1) [2]:(r0+8,c) [3]:(r0+8,c+1)
            float sq00 = xn0 + pn0 - 2.f * acc[mt][nt][0];
            float sq01 = xn0 + pn1 - 2.f * acc[mt][nt][1];
            float sq10 = xn1 + pn0 - 2.f * acc[mt][nt][2];
            float sq11 = xn1 + pn1 - 2.f * acc[mt][nt][3];

            float d00 = sqrtf(fmaxf(sq00, 0.f) + OUT_EPS);
            float d01 = sqrtf(fmaxf(sq01, 0.f) + OUT_EPS);
            float d10 = sqrtf(fmaxf(sq10, 0.f) + OUT_EPS);
            float d11 = sqrtf(fmaxf(sq11, 0.f) + OUT_EPS);

            float s00 = __expf(-temp * d00);
            float s01 = __expf(-temp * d01);
            float s10 = __expf(-temp * d10);
            float s11 = __expf(-temp * d11);

            size_t i0 = (size_t)r0 * M_ROWS + c;
            size_t i1 = (size_t)(r0 + 8) * M_ROWS + c;

            *reinterpret_cast<float2*>(simo + i0)  = make_float2(s00, s01);
            *reinterpret_cast<float2*>(simo + i1)  = make_float2(s10, s11);
            *reinterpret_cast<float2*>(disto + i0) = make_float2(d00, d01);
            *reinterpret_cast<float2*>(disto + i1) = make_float2(d10, d11);
        }
    }
}

// ---------------------------------------------------------------------------
extern "C" void kernel_launch(void* const* d_in, const int* in_sizes, int n_in,
                              void* d_out, int out_size)
{
    (void)in_sizes; (void)n_in; (void)out_size;
    const float* x  = (const float*)d_in[0];
    const float* p  = (const float*)d_in[1];
    const float* fw = (const float*)d_in[2];
    const float* t  = (const float*)d_in[3];
    float* out = (float*)d_out;

    prep_kernel<<<N_ROWS / 8, 256>>>(x, fw, N_ROWS, 0);
    prep_kernel<<<M_ROWS / 8, 256>>>(p, fw, M_ROWS, 1);

    dim3 grid(M_ROWS / BN, N_ROWS / BM);  // (8, 128)
    gemm_kernel<<<grid, 256>>>(t, out);
}